// round 4
// baseline (speedup 1.0000x reference)
#include <cuda_runtime.h>
#include <math.h>
#include <stdint.h>

#define NDIM     128
#define TABK     1024
#define BMAXF    8.0f
#define INV_BMAX 0.125f
#define ATT_SCALE 0.08838834764831845f  // 1/sqrt(128)
#define CAP      1024                    // smem attn cache per graph (nodes)

// -------- persistent device scratch (static allocation only) --------
__device__ float g_M[2][NDIM];               // Wq @ Wk^T
__device__ float g_Kb[2];                    // Wk @ bq
__device__ int   g_start[16384];             // per-graph node offsets
__device__ float g_psi[2][TABK + 1][NDIM];   // charge_embed table psi_j(beta)
__device__ int   g_count;                    // aux completion counter
__device__ int   g_done;                     // aux completion flag

__device__ __forceinline__ float silu_f(float z) {
    return z / (1.0f + expf(-z));
}
__device__ __forceinline__ float softplus_fast(float s) {
    return fmaxf(s, 0.0f) + __logf(1.0f + __expf(-fabsf(s)));
}

__global__ void reset_kernel() {
    g_count = 0;
    g_done  = 0;
}

// ====================== single fused kernel ======================
// block roles by blockIdx.x:
//   [0, 130)             table builder (65 blocks per sign j)
//   [130, 130+SBn)       starts (binary search, 128 graphs per block)
//   130+SBn              prep (M, Kb)
//   [naux, naux+ngraphs) main (1 graph per block)
#define TPB_T 16
#define NTB   65            // ceil(1025/16)
#define NTAB2 (2 * NTB)     // 130
#define NW  4
#define NPB (NW * 4)

__global__ __launch_bounds__(128, 10) void fused_kernel(
    const float* __restrict__ ns, const float* __restrict__ charge,
    const void* __restrict__ batch_raw, int ngraphs, int nnodes, int naux,
    const float* __restrict__ Wq, const float* __restrict__ bq,
    const float* __restrict__ Wk, const float* __restrict__ Wv,
    const float* __restrict__ W1, const float* __restrict__ b1,
    const float* __restrict__ W2, const float* __restrict__ b2,
    float* __restrict__ out) {
    int bid = blockIdx.x;
    int tid = threadIdx.x;

    if (bid < naux) {
        // =================== AUX ROLES ===================
        if (bid < NTAB2) {
            // ---- table: psi_j(beta) for 16 beta points ----
            int j  = bid / NTB;
            int tb = bid - j * NTB;
            int n  = tid;
            float u2 = 0.f;                  // U2[j][n] = Wv[j,:] @ W1[:,n]
            #pragma unroll 8
            for (int ee = 0; ee < NDIM; ee++)
                u2 = fmaf(Wv[j * NDIM + ee], W1[ee * NDIM + n], u2);
            __shared__ float h1s[TPB_T][NDIM];
            float b1n = b1[n];
            #pragma unroll
            for (int tt = 0; tt < TPB_T; tt++) {
                int t = tb * TPB_T + tt;
                if (t > TABK) break;
                float x = (float)t / (float)TABK;
                float beta = BMAXF * x * x;
                h1s[tt][n] = silu_f(fmaf(beta, u2, b1n));
            }
            __syncthreads();
            float b2n = b2[n];
            float wv = Wv[j * NDIM + n];
            for (int tt = 0; tt < TPB_T; tt++) {
                int t = tb * TPB_T + tt;
                if (t > TABK) break;
                float y = 0.f;
                #pragma unroll 8
                for (int d = 0; d < NDIM; d++) y = fmaf(h1s[tt][d], W2[d * NDIM + n], y);
                float x = (float)t / (float)TABK;
                float beta = BMAXF * x * x;
                g_psi[j][t][n] = fmaf(beta, wv, silu_f(y + b2n));
            }
        } else if (bid < naux - 1) {
            // ---- starts: binary search (batch is sorted) ----
            int g = (bid - NTAB2) * 128 + tid;
            if (g <= ngraphs) {
                const int* b32 = (const int*)batch_raw;
                int w = (nnodes >= 8) ? ((nnodes & ~1) - 6) : 0;
                bool is64 = (b32[w + 1] == 0) && (b32[w + 3] == 0) && (b32[w + 5] == 0);
                const long long* b64 = (const long long*)batch_raw;
                long long gv = (long long)g;
                int lo = 0, hi = nnodes;
                while (lo < hi) {
                    int mid = (lo + hi) >> 1;
                    long long val = is64 ? b64[mid] : (long long)b32[mid];
                    if (val < gv) lo = mid + 1; else hi = mid;
                }
                g_start[g] = lo;
            }
        } else {
            // ---- prep: M, Kb ----
            int e = tid;
            float m0 = 0.f, m1 = 0.f;
            for (int d = 0; d < NDIM; d++) {
                float wq = Wq[e * NDIM + d];
                m0 = fmaf(wq, Wk[d], m0);
                m1 = fmaf(wq, Wk[NDIM + d], m1);
            }
            g_M[0][e] = m0;
            g_M[1][e] = m1;
            if (tid < 2) {
                float kb = 0.f;
                for (int d = 0; d < NDIM; d++) kb = fmaf(Wk[tid * NDIM + d], bq[d], kb);
                g_Kb[tid] = kb;
            }
        }
        // publish
        __syncthreads();
        if (tid == 0) {
            __threadfence();
            int c = atomicAdd(&g_count, 1) + 1;
            if (c == naux) {
                __threadfence();
                atomicExch(&g_done, 1);
            }
        }
        return;
    }

    // =================== MAIN ROLE ===================
    int g = bid - naux;
    if (g >= ngraphs) return;

    // wait for aux publication (first wave only pays ~aux duration)
    if (tid == 0) {
        while (atomicAdd(&g_done, 0) == 0) { __nanosleep(200); }
    }
    __syncthreads();
    __threadfence();

    int wid  = tid >> 5, lane = tid & 31;
    int l8   = lane & 7;
    int grp  = lane >> 3;
    __shared__ float warpsum[NW];
    __shared__ float sm_attn[CAP];

    float q  = charge[g];
    float r0 = fmaxf(q, 0.f), r1 = fmaxf(-q, 0.f);
    float c0 = fminf(r0, 1.f), c1 = fminf(r1, 1.f);
    float cg = c0 * g_Kb[0] + c1 * g_Kb[1];
    int   jj = (q < 0.f) ? 1 : 0;
    float qb = fmaxf(r0, r1);
    int n0 = g_start[g], n1 = g_start[g + 1];

    // combined projection Mc = c0*M0 + c1*M1, this lane's 16-float slice
    float4 Mc[4];
    #pragma unroll
    for (int jc = 0; jc < 4; jc++) {
        int e = jc * 32 + l8 * 4;
        float4 a = *reinterpret_cast<const float4*>(&g_M[0][e]);
        float4 b = *reinterpret_cast<const float4*>(&g_M[1][e]);
        Mc[jc].x = c0 * a.x + c1 * b.x;
        Mc[jc].y = c0 * a.y + c1 * b.y;
        Mc[jc].z = c0 * a.z + c1 * b.z;
        Mc[jc].w = c0 * a.w + c1 * b.w;
    }

    // ---- phase A: block-local softplus-attention sum (loads warm L2) ----
    float acc = 0.f;
    for (int base = n0; base < n1; base += NPB) {
        int node = base + wid * 4 + grp;
        bool valid = node < n1;
        float s = 0.f;
        if (valid) {
            const float* row = ns + (long)node * NDIM + l8 * 4;
            #pragma unroll
            for (int jc = 0; jc < 4; jc++) {
                float4 v = *reinterpret_cast<const float4*>(row + jc * 32);
                s += v.x * Mc[jc].x + v.y * Mc[jc].y + v.z * Mc[jc].z + v.w * Mc[jc].w;
            }
        }
        s += __shfl_xor_sync(0xffffffffu, s, 1);
        s += __shfl_xor_sync(0xffffffffu, s, 2);
        s += __shfl_xor_sync(0xffffffffu, s, 4);
        if (valid && l8 == 0) {
            float attn = softplus_fast((s + cg) * ATT_SCALE);
            acc += attn;
            int li = node - n0;
            if (li < CAP) sm_attn[li] = attn;
        }
    }
    #pragma unroll
    for (int o = 16; o > 0; o >>= 1) acc += __shfl_xor_sync(0xffffffffu, acc, o);
    if (lane == 0) warpsum[wid] = acc;
    __syncthreads();
    float asum = warpsum[0] + warpsum[1] + warpsum[2] + warpsum[3];
    float inv = 1.0f / asum;

    // ---- phase B: table epilogue; evict-first reads, streaming stores ----
    for (int base = n0; base < n1; base += NPB) {
        int node = base + wid * 4 + grp;
        if (node >= n1) continue;
        int li = node - n0;
        float attn;
        if (li < CAP) {
            attn = sm_attn[li];
        } else {
            float s = 0.f;
            const float* row = ns + (long)node * NDIM + l8 * 4;
            #pragma unroll
            for (int jc = 0; jc < 4; jc++) {
                float4 v = __ldcs(reinterpret_cast<const float4*>(row + jc * 32));
                s += v.x * Mc[jc].x + v.y * Mc[jc].y + v.z * Mc[jc].z + v.w * Mc[jc].w;
            }
            s += __shfl_xor_sync(0xffffffffu, s, 1);
            s += __shfl_xor_sync(0xffffffffu, s, 2);
            s += __shfl_xor_sync(0xffffffffu, s, 4);
            attn = softplus_fast((s + cg) * ATT_SCALE);
        }
        float beta = attn * inv * qb;
        float tf = (float)TABK * sqrtf(beta * INV_BMAX);
        int idx = (int)tf;
        if (idx > TABK - 1) idx = TABK - 1;
        float f = tf - (float)idx;
        const float* pa = &g_psi[jj][idx][0];
        const float* row = ns + (long)node * NDIM;
        float* orow = out + (long)node * NDIM;
        #pragma unroll
        for (int jc = 0; jc < 4; jc++) {
            int e = jc * 32 + l8 * 4;
            float4 v = __ldcs(reinterpret_cast<const float4*>(row + e));
            float4 a = *reinterpret_cast<const float4*>(pa + e);
            float4 b = *reinterpret_cast<const float4*>(pa + NDIM + e);
            float4 o4;
            o4.x = v.x + fmaf(f, b.x - a.x, a.x);
            o4.y = v.y + fmaf(f, b.y - a.y, a.y);
            o4.z = v.z + fmaf(f, b.z - a.z, a.z);
            o4.w = v.w + fmaf(f, b.w - a.w, a.w);
            __stcs(reinterpret_cast<float4*>(orow + e), o4);
        }
    }
}

extern "C" void kernel_launch(void* const* d_in, const int* in_sizes, int n_in,
                              void* d_out, int out_size) {
    const float* ns     = (const float*)d_in[0];
    const float* charge = (const float*)d_in[1];
    const void*  batch  = (const void*) d_in[2];
    const float* Wq     = (const float*)d_in[3];
    const float* bq     = (const float*)d_in[4];
    const float* Wk     = (const float*)d_in[5];
    const float* Wv     = (const float*)d_in[6];
    const float* W1     = (const float*)d_in[7];
    const float* b1     = (const float*)d_in[8];
    const float* W2     = (const float*)d_in[9];
    const float* b2     = (const float*)d_in[10];
    float* out = (float*)d_out;

    int nnodes  = in_sizes[0] / NDIM;
    int ngraphs = in_sizes[1];

    int sbn  = (ngraphs + 1 + 127) / 128;   // starts blocks
    int naux = NTAB2 + sbn + 1;

    reset_kernel<<<1, 1>>>();
    fused_kernel<<<naux + ngraphs, 128>>>(ns, charge, batch, ngraphs, nnodes, naux,
                                          Wq, bq, Wk, Wv, W1, b1, W2, b2, out);
}